// round 10
// baseline (speedup 1.0000x reference)
#include <cuda_runtime.h>
#include <cuda_bf16.h>

#define BETA   0.001f
#define TPB    256
#define SPB    4        // segments per block (2 warps each)
#define MAXB   2048
#define LOG2E  1.4426950408889634f
#define LN2    0.6931471805599453f

typedef unsigned long long u64;

__device__ float    g_part[MAXB];
__device__ unsigned g_done = 0;

__device__ __forceinline__ float ex2f(float x){ float r; asm("ex2.approx.f32 %0,%1;":"=f"(r):"f"(x)); return r; }
__device__ __forceinline__ float lg2f(float x){ float r; asm("lg2.approx.f32 %0,%1;":"=f"(r):"f"(x)); return r; }

__device__ __forceinline__ u64 pack2(float x, float y){ u64 r; asm("mov.b64 %0,{%1,%2};":"=l"(r):"f"(x),"f"(y)); return r; }
__device__ __forceinline__ void unpack2(u64 v, float& x, float& y){ asm("mov.b64 {%0,%1},%2;":"=f"(x),"=f"(y):"l"(v)); }
__device__ __forceinline__ u64 fma2(u64 a, u64 b, u64 c){ u64 r; asm("fma.rn.f32x2 %0,%1,%2,%3;":"=l"(r):"l"(a),"l"(b),"l"(c)); return r; }
__device__ __forceinline__ u64 mul2(u64 a, u64 b){ u64 r; asm("mul.rn.f32x2 %0,%1,%2;":"=l"(r):"l"(a),"l"(b)); return r; }

// i-chunk at b[0..31] (shared, zero-padded) against NJ j-chunk chains.
// B factors are loaded DIRECTLY as packed f32x2 (ulonglong2 = 2 packed pairs):
// em[] layout lo=even i, hi=odd i matches the packed lanes, no pack MOVs needed.
// Chain j accumulates prod(1 + e[j]*b_i); lg2 every 16 factors (8 per packed
// lane). Factor <= ~2^14.1 (|x|<=4.8), 8/lane -> product <= 2^113 < FLT_MAX.
// e==0 (invalid j) -> contributes 0. Chain 0 is the DIAGONAL chunk (weight 1/2 later).
template<int NJ>
__device__ __forceinline__ void sweepN(const float* __restrict__ b,
                                       const float* __restrict__ e,
                                       float& acc, float& accd)
{
    u64 E[NJ];
    #pragma unroll
    for (int j = 0; j < NJ; ++j) E[j] = pack2(e[j], e[j]);
    const u64 one = 0x3f8000003f800000ull;   // {1.0f, 1.0f}

    float r[NJ];
    #pragma unroll
    for (int j = 0; j < NJ; ++j) r[j] = 0.0f;

    #pragma unroll
    for (int blk = 0; blk < 2; ++blk) {      // 16 elements = 8 packed factors per blk
        const ulonglong2* bb = (const ulonglong2*)(b + blk * 16);
        ulonglong2 q0 = bb[0];               // B0, B1
        ulonglong2 q1 = bb[1];               // B2, B3
        ulonglong2 q2 = bb[2];               // B4, B5
        ulonglong2 q3 = bb[3];               // B6, B7
        #pragma unroll
        for (int j = 0; j < NJ; ++j) {
            u64 P = fma2(one, mul2(E[j], q0.x), one);   // 1 + t0
            u64 t;
            t = mul2(E[j], q0.y); P = fma2(P, t, P);
            t = mul2(E[j], q1.x); P = fma2(P, t, P);
            t = mul2(E[j], q1.y); P = fma2(P, t, P);
            t = mul2(E[j], q2.x); P = fma2(P, t, P);
            t = mul2(E[j], q2.y); P = fma2(P, t, P);
            t = mul2(E[j], q3.x); P = fma2(P, t, P);
            t = mul2(E[j], q3.y); P = fma2(P, t, P);
            float pa, pb; unpack2(P, pa, pb);
            r[j] += lg2f(pa * pb);
        }
    }
    accd += r[0];
    #pragma unroll
    for (int j = 1; j < NJ; ++j) acc += r[j];
}

__global__ void __launch_bounds__(TPB, 6) rm_kernel(
    const float* __restrict__ logits,
    const void*  __restrict__ cu_raw,
    int n_seg,
    float* __restrict__ out)
{
    __shared__ __align__(16) float em[SPB][128];   // e^{-x}, zero-padded
    __shared__ __align__(16) float ep[SPB][128];   // e^{+x}, zero-padded
    __shared__ float partv[SPB][2];
    __shared__ float ws[TPB / 32];
    __shared__ bool  isLast;

    const int tid  = threadIdx.x;
    const int w    = tid >> 5;
    const int lane = tid & 31;
    const int segl = w >> 1;
    const int sub  = w & 1;
    const int s    = blockIdx.x * SPB + segl;
    const bool segv = (s < n_seg);

    int L = 2, C = 0;
    const float* gx = logits;
    if (segv) {
        const int* cu32 = (const int*)cu_raw;
        long long a, bnd;
        if (cu32[1] == 0) {                     // int64 layout (cu[0]=0)
            const long long* cu64 = (const long long*)cu_raw;
            a = cu64[s]; bnd = cu64[s + 1];
        } else {
            a = (long long)cu32[s]; bnd = (long long)cu32[s + 1];
        }
        L = (int)(bnd - a);
        C = (L + 31) >> 5;
        gx = logits + a;
    }

    // Stage: warp `sub` covers chunks {2*sub, 2*sub+1}; sq/wsum partials fold later.
    float sq = 0.0f, wsum = 0.0f;
    if (segv) {
        #pragma unroll
        for (int rr = 0; rr < 2; ++rr) {
            int r = sub * 2 + rr;
            int j = (r << 5) + lane;
            bool valid = (j < L);
            float xv = valid ? gx[j] : 0.0f;
            sq += xv * xv;
            int nv = L - (r << 5); nv = (nv > 32) ? 32 : nv;
            if (valid) wsum += xv * (float)(2 * lane - (nv - 1));
            float xl = xv * LOG2E;
            ep[segl][j] = valid ? ex2f(xl)  : 0.0f;
            em[segl][j] = valid ? ex2f(-xl) : 0.0f;
        }
    }
    __syncthreads();

    // Balanced straight-line split per (C, sub); chain 0 of each sweep is its
    // diagonal (ri,ri). C=4: sub0 (0,*)+(3,3)=5 blocks, sub1 (1,*)+(2,*)=5.
    float acc = 0.0f, accd = 0.0f;
    if (segv) {
        const float* base = em[segl];
        float e[4];
        #pragma unroll
        for (int r = 0; r < 4; ++r) e[r] = ep[segl][(r << 5) + lane];

        if (sub == 0) {
            switch (C) {
                case 1:  sweepN<1>(base, e, acc, accd); break;
                case 2:  sweepN<2>(base, e, acc, accd); break;
                case 3:  sweepN<3>(base, e, acc, accd); break;
                default: sweepN<4>(base,      e,     acc, accd);
                         sweepN<1>(base + 96, e + 3, acc, accd); break;
            }
        } else {
            switch (C) {
                case 1:  break;
                case 2:  sweepN<1>(base + 32, e + 1, acc, accd); break;
                case 3:  sweepN<2>(base + 32, e + 1, acc, accd);
                         sweepN<1>(base + 64, e + 2, acc, accd); break;
                default: sweepN<3>(base + 32, e + 1, acc, accd);
                         sweepN<2>(base + 64, e + 2, acc, accd); break;
            }
        }
    }

    // Fold per-segment uniform coefficients before the warp reduction.
    float v = 0.0f;
    if (segv) {
        float invP = 2.0f / ((float)L * (float)(L - 1));
        v = (acc + 0.5f * accd) * (LN2 * invP)
          + wsum * (0.5f * invP)
          + sq   * (BETA / (float)L);
    }
    #pragma unroll
    for (int o = 16; o > 0; o >>= 1)
        v += __shfl_xor_sync(0xffffffffu, v, o);
    if (lane == 0) {
        if (segv && sub == 0) v -= LN2 / (float)(L - 1);   // diag constant, once
        partv[segl][sub] = v;
    }
    __syncthreads();

    if (tid == 0) {
        float p = 0.0f;
        #pragma unroll
        for (int k = 0; k < SPB; ++k) p += partv[k][0] + partv[k][1];
        g_part[blockIdx.x] = p;
        __threadfence();
        unsigned d = atomicAdd(&g_done, 1u);
        isLast = (d == gridDim.x - 1);
    }
    __syncthreads();

    if (isLast) {
        float t = 0.0f;
        for (int k = tid; k < (int)gridDim.x; k += TPB) t += g_part[k];  // fixed order
        #pragma unroll
        for (int o = 16; o > 0; o >>= 1) t += __shfl_xor_sync(0xffffffffu, t, o);
        if (lane == 0) ws[w] = t;
        __syncthreads();
        if (w == 0) {
            t = (lane < TPB / 32) ? ws[lane] : 0.0f;
            #pragma unroll
            for (int o = 4; o > 0; o >>= 1) t += __shfl_xor_sync(0xffffffffu, t, o);
            if (lane == 0) {
                out[0] = t / (float)n_seg;
                g_done = 0;   // reset for next graph replay
            }
        }
    }
}

extern "C" void kernel_launch(void* const* d_in, const int* in_sizes, int n_in,
                              void* d_out, int out_size) {
    const float* logits = (const float*)d_in[0];
    const void*  cu     = (const void*)d_in[1];
    int n_seg  = in_sizes[1] - 1;
    int blocks = (n_seg + SPB - 1) / SPB;
    if (blocks > MAXB) blocks = MAXB;

    rm_kernel<<<blocks, TPB>>>(logits, cu, n_seg, (float*)d_out);
}